// round 14
// baseline (speedup 1.0000x reference)
#include <cuda_runtime.h>
#include <math.h>

// ---------------------------------------------------------------------------
// PhotonicDelayReservoirAdaptive — sparse delay-tap reservoir scan, sm_103a.
//
//   fb[b,s]  = sum_k softmax(tapw)[k] * sum_r h[b, t-d_k, r] * W_fb[k,r,s]
//   h_new    = 0.9*h + 0.1*tanh(x[b,t]*W_in[s] + fb[b,s] + bias[s])
//
// R13 = R12 (best: 5775us) + 32 warps + compensated packing:
//  * 64 independent CTAs (1 batch each), 1024 threads = 32 warps (8/SMSP).
//    NO cross-CTA sync; ONE __syncthreads per step; static SMEM only.
//  * Warp wg owns 8 columns; each column split across 4 sub-lanes by hist
//    BANK CLASS (sub = e&3): the 4 subs of a column touch disjoint bank
//    sets, so they can never collide; counting-sort by rotated key
//    (((e>>2)&7) - cl) & 7 staggers the 8 same-class lanes across their 8
//    banks. lane = 4*(c%8) + sub.
//  * Schedule in GMEM (read via __ldg -> L1-resident), pair-interleaved
//    [warp][pair][lane][2]: one coalesced 256B LDG.64 per warp per pair.
//    Per-warp CSR base offsets (variable pair counts) keep the accessed
//    footprint ~190KB < 218KB L1. History prefetch uses __ldcg (L2-direct)
//    so the schedule is the ONLY L1 resident.
//  * COMPENSATED packing: word = ((bits(v*tw) - idx + 0x400) & ~0x7FF) | idx
//    -> the raw 32-bit word, reinterpreted as f32, is within a half-ulp
//    (at bit 11) of the true weight. Inner loop uses the word directly as
//    the FFMA multiplier: per entry = LOP3(idx) + addr + LDS + FFMA only.
//  * Per-warp UNIFORM trip counts; pads are neutral (value = lane -> FTZ-0
//    denormal, hist bank = lane's own class slot -> conflict-free).
//  * hist[2][5*256] static double buffer; slot0 = row t-1 (written locally),
//    slots 1-4 = rows t-{4,24,96,168} prefetched one step early via __ldcg
//    from this CTA's own write-once gmem history.
// ---------------------------------------------------------------------------

#define T_LEN     2048
#define R_DIM     256
#define N_TAPS    5
#define NTH       1024
#define NWARP     32
#define NBATCH    64
#define CAP_SUB   64       // entries per sub-list: mean 32, sigma 5.6 -> +5.7s
#define CAP_PAIRW 32       // pair-blocks per warp cap

#define SCHED_WORDS (NWARP * CAP_PAIRW * 64)   // 65536 words = 256 KB (gmem)

__device__ __align__(16) unsigned g_sched[SCHED_WORDS];
__device__ int g_warpBase[NWARP];    // pair-block base per warp
__device__ int g_warpPairs[NWARP];   // pair count per warp (uniform trips)

// ---------------------------------------------------------------------------
// Builder: 1 CTA, 256 threads, thread = output column c (wg = c/8, cl = c%8).
// ---------------------------------------------------------------------------
__global__ void build_kernel(const float* __restrict__ W_fb,
                             const float* __restrict__ tapw) {
    __shared__ int scnt[R_DIM][32];   // [col][sub*8 + key]
    __shared__ int swMaxE[NWARP];     // per-warp max entries over its 32 lanes
    __shared__ int sBase[NWARP];

    const int c  = threadIdx.x;
    const int wg = c >> 3;
    const int cl = c & 7;

    // softmax of tap weights (exact, redundant per thread)
    float tw[N_TAPS];
    {
        float m = tapw[0];
        #pragma unroll
        for (int k = 1; k < N_TAPS; k++) m = fmaxf(m, tapw[k]);
        float sum = 0.f;
        #pragma unroll
        for (int k = 0; k < N_TAPS; k++) { tw[k] = expf(tapw[k] - m); sum += tw[k]; }
        #pragma unroll
        for (int k = 0; k < N_TAPS; k++) tw[k] /= sum;
    }

    if (c < NWARP) swMaxE[c] = 0;
    // pad-fill the whole schedule: word i -> its lane position (i>>1)&31.
    // A pad read yields e = lane: value denormal ~0; bank class e&3 == the
    // lane's own sub, class slot (e>>2)&7 == cl -> conflict-free.
    for (int i = c; i < SCHED_WORDS; i += R_DIM)
        g_sched[i] = (unsigned)((i >> 1) & 31);
    #pragma unroll
    for (int bkt = 0; bkt < 32; bkt++) scnt[c][bkt] = 0;
    __syncthreads();

    // pass 1: bucket counts (coalesced over c across lanes)
    for (int k = 0; k < N_TAPS; k++)
        for (int r = 0; r < R_DIM; r++) {
            float v = W_fb[(k * R_DIM + r) * R_DIM + c];
            if (v != 0.f) {
                int e = k * R_DIM + r;
                int sub = e & 3;
                int key = (((e >> 2) & 7) - cl) & 7;
                scnt[c][sub * 8 + key]++;
            }
        }

    // exclusive prefix within each sub's 8 buckets; track per-column max sub
    int mymax = 0;
    #pragma unroll
    for (int sub = 0; sub < 4; sub++) {
        int acc = 0;
        #pragma unroll
        for (int bkt = 0; bkt < 8; bkt++) {
            int v = scnt[c][sub * 8 + bkt];
            scnt[c][sub * 8 + bkt] = acc;
            acc += v;
        }
        if (acc > mymax) mymax = acc;
    }
    atomicMax(&swMaxE[wg], mymax < CAP_SUB ? mymax : CAP_SUB);
    __syncthreads();

    if (c == 0) {
        int base = 0;
        for (int w = 0; w < NWARP; w++) {
            sBase[w] = base;
            int pr = (swMaxE[w] + 1) >> 1;
            if (pr < 1) pr = 1;
            if (pr > CAP_PAIRW) pr = CAP_PAIRW;
            g_warpBase[w]  = base;
            g_warpPairs[w] = pr;
            base += pr;
        }
    }
    __syncthreads();

    // pass 2: scatter, compensated rounding (raw word ~= true weight)
    const int base = sBase[wg];
    for (int k = 0; k < N_TAPS; k++) {
        const float twk = tw[k];
        for (int r = 0; r < R_DIM; r++) {
            float v = W_fb[(k * R_DIM + r) * R_DIM + c];
            if (v != 0.f) {
                unsigned e = (unsigned)(k * R_DIM + r);
                int sub = e & 3;
                int key = (((e >> 2) & 7) - cl) & 7;
                int j = scnt[c][sub * 8 + key]++;
                if (j < CAP_SUB) {
                    unsigned fu = __float_as_uint(v * twk);
                    unsigned w32 = ((fu - e + 0x400u) & ~0x7FFu) | e;
                    const int lane = cl * 4 + sub;
                    g_sched[(base + (j >> 1)) * 64 + lane * 2 + (j & 1)] = w32;
                }
            }
        }
    }
}

// ---------------------------------------------------------------------------
// Main: 64 independent CTAs (one batch each), 1024 threads, static SMEM only.
// ---------------------------------------------------------------------------
__global__ void __launch_bounds__(NTH, 1)
reservoir_kernel(const float* __restrict__ x,
                 const float* __restrict__ W_in,
                 const float* __restrict__ bias,
                 float* __restrict__ out) {
    __shared__ float hist[2][5 * R_DIM];   // 10240 B static

    const int tid  = threadIdx.x;
    const int wg   = tid >> 5;
    const int lane = tid & 31;
    const int c    = wg * 8 + (lane >> 2);    // owned column
    const int b    = blockIdx.x;

    for (int i = tid; i < 2 * 5 * R_DIM; i += NTH) hist[0][i] = 0.f;

    const int RP = g_warpPairs[wg];           // uniform per warp
    const float w_in_c = W_in[c];
    const float bias_c = bias[c];
    const float* xr = x + (size_t)b * T_LEN;
    float* ob = out + (size_t)b * T_LEN * R_DIM;

    // prefetch staging roles: quarter q stages slot q+1 (row t - {3,23,95,167})
    const int q    = tid >> 8;                // 0..3
    const int col2 = tid & 255;
    const int dly  = (q == 0) ? 3 : (q == 1) ? 23 : (q == 2) ? 95 : 167;

    float h  = 0.f;
    float xc = __ldg(xr);
    __syncthreads();

    // my pair stream: pair p at uint2 slot [ (base+p)*32 + lane ]
    const uint2* sp2 = (const uint2*)g_sched + (size_t)g_warpBase[wg] * 32 + lane;

    for (int t = 0; t < T_LEN; t++) {
        const float* cur = hist[t & 1];
        float*       nxt = hist[(t + 1) & 1];

        // prefetch row (t+1)-(dly+1) for slot q+1 via __ldcg (L2-direct,
        // keeps L1 exclusively for the schedule) + next x (broadcast)
        const float pq = (t >= dly)
            ? __ldcg(ob + (size_t)(t - dly) * R_DIM + col2) : 0.f;
        const float xn = (t + 1 < T_LEN) ? __ldg(xr + t + 1) : 0.f;

        // sparse gather: raw word is the weight (compensated packing),
        // low 11 bits are the hist index; pads contribute denormal*h ~ 0
        float a0 = 0.f, a1 = 0.f;
        #pragma unroll 4
        for (int p = 0; p < RP; p++) {
            const uint2 e = __ldg(&sp2[p * 32]);
            a0 = fmaf(__uint_as_float(e.x), cur[e.x & 0x7FFu], a0);
            a1 = fmaf(__uint_as_float(e.y), cur[e.y & 0x7FFu], a1);
        }
        float acc = a0 + a1;
        acc += __shfl_xor_sync(0xffffffffu, acc, 1);   // combine 4 sub-lanes
        acc += __shfl_xor_sync(0xffffffffu, acc, 2);

        // all 4 sub-lanes compute h (same inputs); sub0 stores
        h = 0.9f * h + 0.1f * tanhf(fmaf(xc, w_in_c, acc) + bias_c);
        if ((lane & 3) == 0) {
            ob[(size_t)t * R_DIM + c] = h;
            nxt[c] = h;                                 // slot0 = row t (d=1)
        }

        // stage slot q+1: row (t+1)-{4,24,96,168} = t-dly
        nxt[(q + 1) * R_DIM + col2] = pq;
        xc = xn;

        __syncthreads();   // the ONLY per-step synchronization
    }
}

// ---------------------------------------------------------------------------
extern "C" void kernel_launch(void* const* d_in, const int* in_sizes, int n_in,
                              void* d_out, int out_size) {
    const float* x           = (const float*)d_in[0];  // (64, 2048, 1)
    const float* W_in        = (const float*)d_in[1];  // (256, 1)
    const float* W_fb        = (const float*)d_in[2];  // (5, 256, 256)
    const float* tap_weights = (const float*)d_in[3];  // (5,)
    const float* bias        = (const float*)d_in[4];  // (256,)
    float* out = (float*)d_out;                        // (64, 2048, 256)

    (void)in_sizes; (void)n_in; (void)out_size;

    build_kernel<<<1, R_DIM>>>(W_fb, tap_weights);
    reservoir_kernel<<<NBATCH, NTH>>>(x, W_in, bias, out);
}

// round 15
// speedup vs baseline: 1.7068x; 1.7068x over previous
#include <cuda_runtime.h>
#include <math.h>

// ---------------------------------------------------------------------------
// PhotonicDelayReservoirAdaptive — sparse delay-tap reservoir scan, sm_103a.
//
//   fb[b,s]  = sum_k softmax(tapw)[k] * sum_r h[b, t-d_k, r] * W_fb[k,r,s]
//   h_new    = 0.9*h + 0.1*tanh(x[b,t]*W_in[s] + fb[b,s] + bias[s])
//
// R14 = R12 shape (best: 5775us; 512 thr, 16 warps — R13 proved more warps
// scale the fixed per-warp overhead) + instruction diet on the gather:
//  * 64 independent CTAs (1 batch each), 512 threads. NO cross-CTA sync,
//    ONE __syncthreads per step, static SMEM only (10 KB hist).
//  * Warp wg owns 16 columns; column split across 2 sub-lanes by hist-bank
//    PARITY (sub = e&1; subs can never collide), counting-sorted by rotated
//    key (((e>>1)&15) - cl)&15 to stagger same-parity lanes across banks.
//  * COMPENSATED packing (validated R13, rel_err 8.0e-6): schedule word =
//    ((bits(v*tw) - e + 0x400) & ~0x7FF) | e  -> the raw word IS the f32
//    weight (within half a bit-11 ulp); low 11 bits = hist index. Inner
//    loop: LOP3(idx) + LDS + FFMA per entry, no value mask.
//  * LDG.128 QUADS: schedule pair-interleaved [wg][quad][lane][4]; one
//    coalesced 512B warp load serves 4 entries/lane. 4 accumulators.
//  * Per-warp uniform quad counts with neutral pads (pad word = lane:
//    denormal value ~0, hist bank = lane -> conflict-free), per-warp base
//    offsets keep accessed L1 footprint ~180KB < 218KB.
//  * History prefetch via __ldcg (L2-direct, no L1 pollution): schedule is
//    the only L1 resident. hist[2][5*256] double buffer; slot0 = row t-1
//    written locally, slots 1-4 prefetched one step early.
// ---------------------------------------------------------------------------

#define T_LEN     2048
#define R_DIM     256
#define N_TAPS    5
#define NTH       512
#define NWARP     16
#define NBATCH    64
#define CAP_SUB   96     // entries per sub-list (mean 64, sigma 7.6 -> +4.2s)
#define CAP_QUAD  24     // quad-blocks per warp cap = ceil(CAP_SUB/4)

#define SCHED_WORDS (NWARP * CAP_QUAD * 128)   // 49152 words = 196608 B

__device__ __align__(16) unsigned g_sched[SCHED_WORDS];
__device__ int g_warpBase[NWARP];    // quad-block base per warp
__device__ int g_warpQuads[NWARP];   // quad count per warp (uniform trips)

// ---------------------------------------------------------------------------
// Builder: 1 CTA, 256 threads, thread = output column c (wg=c/16, cl=c%16).
// ---------------------------------------------------------------------------
__global__ void build_kernel(const float* __restrict__ W_fb,
                             const float* __restrict__ tapw) {
    __shared__ int scnt[R_DIM][32];   // [col][sub*16 + key]
    __shared__ int swMaxE[NWARP];
    __shared__ int sBase[NWARP];

    const int c  = threadIdx.x;
    const int wg = c >> 4;
    const int cl = c & 15;

    // softmax of tap weights (exact, redundant per thread)
    float tw[N_TAPS];
    {
        float m = tapw[0];
        #pragma unroll
        for (int k = 1; k < N_TAPS; k++) m = fmaxf(m, tapw[k]);
        float sum = 0.f;
        #pragma unroll
        for (int k = 0; k < N_TAPS; k++) { tw[k] = expf(tapw[k] - m); sum += tw[k]; }
        #pragma unroll
        for (int k = 0; k < N_TAPS; k++) tw[k] /= sum;
    }

    if (c < NWARP) swMaxE[c] = 0;
    // pad-fill: word = its own lane -> denormal value (~0 after FTZ), hist
    // bank = lane (distinct per lane, parity matches the lane's sub class).
    for (int i = c; i < SCHED_WORDS; i += R_DIM)
        g_sched[i] = (unsigned)((i >> 2) & 31);
    #pragma unroll
    for (int bkt = 0; bkt < 32; bkt++) scnt[c][bkt] = 0;
    __syncthreads();

    // pass 1: bucket counts (coalesced over c across lanes)
    for (int k = 0; k < N_TAPS; k++)
        for (int r = 0; r < R_DIM; r++) {
            float v = W_fb[(k * R_DIM + r) * R_DIM + c];
            if (v != 0.f) {
                int e = k * R_DIM + r;
                int sub = e & 1;
                int key = (((e >> 1) & 15) - cl) & 15;
                scnt[c][sub * 16 + key]++;
            }
        }

    // exclusive prefix within each parity partition; track per-column max
    int mymax = 0;
    #pragma unroll
    for (int sub = 0; sub < 2; sub++) {
        int acc = 0;
        #pragma unroll
        for (int bkt = 0; bkt < 16; bkt++) {
            int v = scnt[c][sub * 16 + bkt];
            scnt[c][sub * 16 + bkt] = acc;
            acc += v;
        }
        if (acc > mymax) mymax = acc;
    }
    atomicMax(&swMaxE[wg], mymax < CAP_SUB ? mymax : CAP_SUB);
    __syncthreads();

    if (c == 0) {
        int base = 0;
        for (int w = 0; w < NWARP; w++) {
            int qd = (swMaxE[w] + 3) >> 2;
            if (qd < 1) qd = 1;
            if (qd > CAP_QUAD) qd = CAP_QUAD;
            sBase[w] = base;
            g_warpBase[w]  = base;
            g_warpQuads[w] = qd;
            base += qd;
        }
    }
    __syncthreads();

    // pass 2: scatter, compensated rounding (raw word ~= true weight)
    const int base = sBase[wg];
    for (int k = 0; k < N_TAPS; k++) {
        const float twk = tw[k];
        for (int r = 0; r < R_DIM; r++) {
            float v = W_fb[(k * R_DIM + r) * R_DIM + c];
            if (v != 0.f) {
                unsigned e = (unsigned)(k * R_DIM + r);
                int sub = e & 1;
                int key = (((e >> 1) & 15) - cl) & 15;
                int j = scnt[c][sub * 16 + key]++;
                if (j < CAP_SUB) {
                    unsigned fu  = __float_as_uint(v * twk);
                    unsigned w32 = ((fu - e + 0x400u) & ~0x7FFu) | e;
                    const int lane = cl * 2 + sub;
                    g_sched[(base + (j >> 2)) * 128 + lane * 4 + (j & 3)] = w32;
                }
            }
        }
    }
}

// ---------------------------------------------------------------------------
// Main: 64 independent CTAs (one batch each), 512 threads, static SMEM only.
// ---------------------------------------------------------------------------
__global__ void __launch_bounds__(NTH, 1)
reservoir_kernel(const float* __restrict__ x,
                 const float* __restrict__ W_in,
                 const float* __restrict__ bias,
                 float* __restrict__ out) {
    __shared__ float hist[2][5 * R_DIM];   // 10240 B static

    const int tid  = threadIdx.x;
    const int wg   = tid >> 5;
    const int lane = tid & 31;
    const int c    = wg * 16 + (lane >> 1);   // owned column
    const int b    = blockIdx.x;

    for (int i = tid; i < 2 * 5 * R_DIM; i += NTH) hist[0][i] = 0.f;

    const int QD = g_warpQuads[wg];           // uniform per warp
    const float w_in_c = W_in[c];
    const float bias_c = bias[c];
    const float* xr = x + (size_t)b * T_LEN;
    float* ob = out + (size_t)b * T_LEN * R_DIM;

    // prefetch staging roles: threads 0-255 stage slots 1,2; 256-511 slots 3,4
    const int q    = tid >> 8;
    const int col2 = tid & 255;

    float h  = 0.f;
    float xc = __ldg(xr);
    __syncthreads();

    // my quad stream: quad p = uint4 slot [(base+p)*32 + lane]
    const uint4* sp4 = (const uint4*)g_sched + (size_t)g_warpBase[wg] * 32 + lane;

    for (int t = 0; t < T_LEN; t++) {
        const float* cur = hist[t & 1];
        float*       nxt = hist[(t + 1) & 1];

        // prefetch rows for step t+1 from this CTA's own write-once history
        // (__ldcg: L2-direct, keeps L1 exclusively for the schedule) + next x
        float p0, p1;
        if (q == 0) {
            p0 = (t >= 3)  ? __ldcg(ob + (size_t)(t - 3)  * R_DIM + col2) : 0.f;
            p1 = (t >= 23) ? __ldcg(ob + (size_t)(t - 23) * R_DIM + col2) : 0.f;
        } else {
            p0 = (t >= 95)  ? __ldcg(ob + (size_t)(t - 95)  * R_DIM + col2) : 0.f;
            p1 = (t >= 167) ? __ldcg(ob + (size_t)(t - 167) * R_DIM + col2) : 0.f;
        }
        const float xn = (t + 1 < T_LEN) ? __ldg(xr + t + 1) : 0.f;

        // sparse gather: LDG.128 (4 entries), raw word = weight, 11-bit idx,
        // 4 independent accumulators; pads contribute denormal*h ~ 0
        float a0 = 0.f, a1 = 0.f, a2 = 0.f, a3 = 0.f;
        #pragma unroll 4
        for (int p = 0; p < QD; p++) {
            const uint4 e = __ldg(&sp4[p * 32]);
            a0 = fmaf(__uint_as_float(e.x), cur[e.x & 0x7FFu], a0);
            a1 = fmaf(__uint_as_float(e.y), cur[e.y & 0x7FFu], a1);
            a2 = fmaf(__uint_as_float(e.z), cur[e.z & 0x7FFu], a2);
            a3 = fmaf(__uint_as_float(e.w), cur[e.w & 0x7FFu], a3);
        }
        float acc = (a0 + a1) + (a2 + a3);
        acc += __shfl_xor_sync(0xffffffffu, acc, 1);   // combine sub-lanes

        // both sub-lanes compute h (same inputs); sub0 stores
        h = 0.9f * h + 0.1f * tanhf(fmaf(xc, w_in_c, acc) + bias_c);
        if ((lane & 1) == 0) {
            ob[(size_t)t * R_DIM + c] = h;
            nxt[c] = h;                                 // slot0 = row t (d=1)
        }

        // stage slots 1-4: rows (t+1)-{4,24,96,168} = t-3, t-23, t-95, t-167
        if (q == 0) {
            nxt[1 * R_DIM + col2] = p0;
            nxt[2 * R_DIM + col2] = p1;
        } else {
            nxt[3 * R_DIM + col2] = p0;
            nxt[4 * R_DIM + col2] = p1;
        }
        xc = xn;

        __syncthreads();   // the ONLY per-step synchronization
    }
}

// ---------------------------------------------------------------------------
extern "C" void kernel_launch(void* const* d_in, const int* in_sizes, int n_in,
                              void* d_out, int out_size) {
    const float* x           = (const float*)d_in[0];  // (64, 2048, 1)
    const float* W_in        = (const float*)d_in[1];  // (256, 1)
    const float* W_fb        = (const float*)d_in[2];  // (5, 256, 256)
    const float* tap_weights = (const float*)d_in[3];  // (5,)
    const float* bias        = (const float*)d_in[4];  // (256,)
    float* out = (float*)d_out;                        // (64, 2048, 256)

    (void)in_sizes; (void)n_in; (void)out_size;

    build_kernel<<<1, R_DIM>>>(W_fb, tap_weights);
    reservoir_kernel<<<NBATCH, NTH>>>(x, W_in, bias, out);
}